// round 4
// baseline (speedup 1.0000x reference)
#include <cuda_runtime.h>
#include <math.h>

#define TT 256
#define BB 64
#define HH 1024
#define PP 128
#define SLOT (HH*BB)   // 65536 floats per time-slot, k-major [k][b]

typedef unsigned long long ull;

// Static scratch (no runtime allocation).
__device__ float g_xT[TT*PP*BB];        // x_in transposed [t][p][b], 8 MB
__device__ float g_h1[(TT+1)*SLOT];     // layer0 hidden seq, slot t+1 = h1(t), 67 MB
__device__ float g_h2[(TT+1)*SLOT];     // layer1 hidden seq, 67 MB
__device__ float g_c0[SLOT];
__device__ float g_c1[SLOT];

__device__ __forceinline__ void ffma2(ull& d, ull a, ull b) {
    asm("fma.rn.f32x2 %0, %1, %2, %0;" : "+l"(d) : "l"(a), "l"(b));
}
__device__ __forceinline__ ull pack2(float x) {
    unsigned u = __float_as_uint(x);
    return ((ull)u << 32) | (ull)u;
}
__device__ __forceinline__ float2 unpack2(ull v) {
    float2 f;
    f.x = __uint_as_float((unsigned)(v & 0xffffffffull));
    f.y = __uint_as_float((unsigned)(v >> 32));
    return f;
}
__device__ __forceinline__ float sigf(float x) { return 1.0f / (1.0f + __expf(-x)); }

// acc[4] (packed f32x2 pairs) += tile of W[grow(r)][k] * HT[k][b]
// grow(r) = (r>>3)*gStride + rowBase + (r&7); lane=row(32), warp=batch octet(8).
// Each thread owns 8 outputs: (row=lane, b = wg*8 .. wg*8+7).
__device__ __forceinline__ void gemm_tile(ull acc[4], const float* __restrict__ W,
                                          int ldw, int rowBase, int gStride,
                                          const float* __restrict__ HT, int K,
                                          float* Ws, float* Hs) {
    const int tid = threadIdx.x, lane = tid & 31, wg = tid >> 5;
    for (int k0 = 0; k0 < K; k0 += 64) {
        // Stage W chunk [32 rows][64 k] into smem, pitch 65 (conflict-free reads).
        #pragma unroll
        for (int q = 0; q < 2; q++) {
            int f = tid * 2 + q;              // 0..511 float4 ids
            int r = f >> 4, kc = (f & 15) << 2;
            int grow = (r >> 3) * gStride + rowBase + (r & 7);
            float4 wv = *(const float4*)(W + (size_t)grow * ldw + k0 + kc);
            float* dst = Ws + r * 65 + kc;
            dst[0] = wv.x; dst[1] = wv.y; dst[2] = wv.z; dst[3] = wv.w;
        }
        // Stage act chunk [64 k][64 b] (contiguous in k-major global layout).
        #pragma unroll
        for (int q = 0; q < 4; q++) {
            int f = tid + (q << 8);           // 0..1023 float4 ids
            int kk = f >> 4, b4 = (f & 15) << 2;
            *(float4*)(Hs + kk * 64 + b4) =
                *(const float4*)(HT + (size_t)(k0 + kk) * 64 + b4);
        }
        __syncthreads();
        const float* wrow = Ws + lane * 65;   // per-lane distinct banks
        const float* hbase = Hs + (wg << 3);  // warp-uniform -> broadcast
        #pragma unroll
        for (int kk = 0; kk < 64; kk++) {
            ull wp = pack2(wrow[kk]);
            const ulonglong2* hp = (const ulonglong2*)(hbase + (kk << 6));
            ulonglong2 h01 = hp[0], h23 = hp[1];
            ffma2(acc[0], h01.x, wp);
            ffma2(acc[1], h01.y, wp);
            ffma2(acc[2], h23.x, wp);
            ffma2(acc[3], h23.y, wp);
        }
        __syncthreads();
    }
}

// Build x_in transposed: g_xT[t][p][b] = t==0 ? start[p] : target[b][t-1][p]
__global__ void trans_kernel(const float* __restrict__ target,
                             const float* __restrict__ start) {
    int gid = blockIdx.x * 256 + threadIdx.x;       // 0 .. 2097151
    int t = gid >> 13, p = (gid >> 6) & 127, b = gid & 63;
    g_xT[gid] = (t == 0) ? start[p]
                         : target[(size_t)b * (TT * PP) + (t - 1) * PP + p];
}

// h0 = z @ fc_init_w^T + fc_init_b  -> slot 0 of both hidden seqs; zero c.
__global__ void init_kernel(const float* __restrict__ z,
                            const float* __restrict__ fw,
                            const float* __restrict__ fb) {
    int idx = blockIdx.x * 256 + threadIdx.x;       // 0 .. 65535 = k*64+b
    int k = idx >> 6, b = idx & 63;
    float a = fb[k];
    const float* zr = z + b * 256;
    const float* wr = fw + (size_t)k * 256;
    #pragma unroll 4
    for (int l = 0; l < 256; l++) a += zr[l] * wr[l];
    g_h1[idx] = a;
    g_h2[idx] = a;
    g_c0[idx] = 0.0f;
    g_c1[idx] = 0.0f;
}

// Pipelined stage s: blocks 0-127 = layer0 step s, blocks 128-255 = layer1 step s-1.
__global__ __launch_bounds__(256) void step_kernel(int s,
    const float* __restrict__ Wih0, const float* __restrict__ Whh0,
    const float* __restrict__ bi0,  const float* __restrict__ bh0,
    const float* __restrict__ Wih1, const float* __restrict__ Whh1,
    const float* __restrict__ bi1,  const float* __restrict__ bh1) {
    __shared__ __align__(16) float sW[32 * 65];
    __shared__ __align__(16) float sH[64 * 64];
    int layer = blockIdx.x >> 7, tile = blockIdx.x & 127;
    if (layer == 0 && s == TT) return;
    if (layer == 1 && s == 0) return;

    ull acc[4] = {0, 0, 0, 0};
    const float *bia, *bib;
    float *cst, *hout;
    if (layer == 0) {
        gemm_tile(acc, Wih0, PP, tile * 8, HH, g_xT + (size_t)s * (PP * BB), PP, sW, sH);
        gemm_tile(acc, Whh0, HH, tile * 8, HH, g_h1 + (size_t)s * SLOT, HH, sW, sH);
        hout = g_h1 + (size_t)(s + 1) * SLOT;
        cst = g_c0; bia = bi0; bib = bh0;
    } else {
        int t = s - 1;
        gemm_tile(acc, Wih1, HH, tile * 8, HH, g_h1 + (size_t)(t + 1) * SLOT, HH, sW, sH);
        gemm_tile(acc, Whh1, HH, tile * 8, HH, g_h2 + (size_t)t * SLOT, HH, sW, sH);
        hout = g_h2 + (size_t)(t + 1) * SLOT;
        cst = g_c1; bia = bi1; bib = bh1;
    }

    // Dump acc tile to smem (pitch 65: bank-conflict-free), remap to (hcol, b).
    int lane = threadIdx.x & 31, wg = threadIdx.x >> 5;
    #pragma unroll
    for (int j = 0; j < 4; j++) {
        float2 v = unpack2(acc[j]);
        sW[lane * 65 + wg * 8 + 2 * j]     = v.x;
        sW[lane * 65 + wg * 8 + 2 * j + 1] = v.y;
    }
    __syncthreads();
    #pragma unroll
    for (int q = 0; q < 2; q++) {
        int c = threadIdx.x * 2 + q;     // 0..511 = hl*64 + b
        int hl = c >> 6, b = c & 63;
        int col = tile * 8 + hl;
        float gi = sW[hl * 65 + b]        + bia[col]          + bib[col];
        float gf = sW[(8 + hl) * 65 + b]  + bia[HH + col]     + bib[HH + col];
        float gg = sW[(16 + hl) * 65 + b] + bia[2 * HH + col] + bib[2 * HH + col];
        float go = sW[(24 + hl) * 65 + b] + bia[3 * HH + col] + bib[3 * HH + col];
        float cc = sigf(gf) * cst[col * 64 + b] + sigf(gi) * tanhf(gg);
        cst[col * 64 + b] = cc;
        hout[col * 64 + b] = sigf(go) * tanhf(cc);
    }
}

// out[b][t][p] = sigmoid(h2(t) . out_w[p] + out_b[p]); grid = T*4 blocks.
__global__ __launch_bounds__(256) void out_kernel(const float* __restrict__ Wout,
                                                  const float* __restrict__ bout,
                                                  float* __restrict__ out) {
    __shared__ __align__(16) float sW[32 * 65];
    __shared__ __align__(16) float sH[64 * 64];
    int t = blockIdx.x >> 2, pt = blockIdx.x & 3;
    ull acc[4] = {0, 0, 0, 0};
    // gStride=8 makes grow(r) = pt*32 + r (plain consecutive rows).
    gemm_tile(acc, Wout, HH, pt * 32, 8, g_h2 + (size_t)(t + 1) * SLOT, HH, sW, sH);
    int lane = threadIdx.x & 31, wg = threadIdx.x >> 5;
    int p = pt * 32 + lane;
    float bo = bout[p];
    #pragma unroll
    for (int j = 0; j < 4; j++) {
        float2 v = unpack2(acc[j]);
        int b0 = wg * 8 + 2 * j;
        out[(size_t)b0 * (TT * PP) + t * PP + p]       = sigf(v.x + bo);
        out[(size_t)(b0 + 1) * (TT * PP) + t * PP + p] = sigf(v.y + bo);
    }
}

extern "C" void kernel_launch(void* const* d_in, const int* in_sizes, int n_in,
                              void* d_out, int out_size) {
    const float* z      = (const float*)d_in[0];
    const float* target = (const float*)d_in[1];
    const float* fw     = (const float*)d_in[2];
    const float* fb     = (const float*)d_in[3];
    const float* start  = (const float*)d_in[4];
    const float* Wih0   = (const float*)d_in[5];
    const float* Whh0   = (const float*)d_in[6];
    const float* bi0    = (const float*)d_in[7];
    const float* bh0    = (const float*)d_in[8];
    const float* Wih1   = (const float*)d_in[9];
    const float* Whh1   = (const float*)d_in[10];
    const float* bi1    = (const float*)d_in[11];
    const float* bh1    = (const float*)d_in[12];
    const float* outw   = (const float*)d_in[13];
    const float* outb   = (const float*)d_in[14];
    float* out = (float*)d_out;

    trans_kernel<<<(TT * PP * BB) / 256, 256>>>(target, start);
    init_kernel<<<SLOT / 256, 256>>>(z, fw, fb);
    for (int s = 0; s <= TT; s++)
        step_kernel<<<256, 256>>>(s, Wih0, Whh0, bi0, bh0, Wih1, Whh1, bi1, bh1);
    out_kernel<<<TT * 4, 256>>>(outw, outb, out);
}

// round 5
// speedup vs baseline: 1.1447x; 1.1447x over previous
#include <cuda_runtime.h>
#include <math.h>

#define TT 256
#define BB 64
#define HH 1024
#define PP 128
#define SLOT (HH*BB)   // 65536 floats per time-slot, k-major [k][b]

typedef unsigned long long ull;

// Static scratch (no runtime allocation).
__device__ float g_xT[TT*PP*BB];        // x_in transposed [t][p][b], 8 MB
__device__ float g_h1[(TT+1)*SLOT];     // layer0 hidden seq, slot t+1 = h1(t), 67 MB
__device__ float g_h2[(TT+1)*SLOT];     // layer1 hidden seq, 67 MB
__device__ float g_c0[SLOT];
__device__ float g_c1[SLOT];

__device__ __forceinline__ void ffma2(ull& d, ull a, ull b) {
    asm("fma.rn.f32x2 %0, %1, %2, %0;" : "+l"(d) : "l"(a), "l"(b));
}
__device__ __forceinline__ ull pack2(float x) {
    unsigned u = __float_as_uint(x);
    return ((ull)u << 32) | (ull)u;
}
__device__ __forceinline__ float2 unpack2(ull v) {
    float2 f;
    f.x = __uint_as_float((unsigned)(v & 0xffffffffull));
    f.y = __uint_as_float((unsigned)(v >> 32));
    return f;
}
__device__ __forceinline__ float sigf(float x) { return 1.0f / (1.0f + __expf(-x)); }

// acc[4] (packed f32x2 pairs) += tile of W[grow(r)][k] * HT[k][b]
// grow(r) = (r>>3)*gStride + rowBase + (r&7); lane=row(32), warp=batch octet(8).
// Each thread owns 8 outputs: (row=lane, b = wg*8 .. wg*8+7).
__device__ __forceinline__ void gemm_tile(ull acc[4], const float* __restrict__ W,
                                          int ldw, int rowBase, int gStride,
                                          const float* __restrict__ HT, int K,
                                          float* Ws, float* Hs) {
    const int tid = threadIdx.x, lane = tid & 31, wg = tid >> 5;
    for (int k0 = 0; k0 < K; k0 += 64) {
        // Stage W chunk [32 rows][64 k] into smem, pitch 65 (conflict-free reads).
        #pragma unroll
        for (int q = 0; q < 2; q++) {
            int f = tid * 2 + q;              // 0..511 float4 ids
            int r = f >> 4, kc = (f & 15) << 2;
            int grow = (r >> 3) * gStride + rowBase + (r & 7);
            float4 wv = *(const float4*)(W + (size_t)grow * ldw + k0 + kc);
            float* dst = Ws + r * 65 + kc;
            dst[0] = wv.x; dst[1] = wv.y; dst[2] = wv.z; dst[3] = wv.w;
        }
        // Stage act chunk [64 k][64 b] (contiguous in k-major global layout).
        #pragma unroll
        for (int q = 0; q < 4; q++) {
            int f = tid + (q << 8);           // 0..1023 float4 ids
            int kk = f >> 4, b4 = (f & 15) << 2;
            *(float4*)(Hs + kk * 64 + b4) =
                *(const float4*)(HT + (size_t)(k0 + kk) * 64 + b4);
        }
        __syncthreads();
        const float* wrow = Ws + lane * 65;   // per-lane distinct banks
        const float* hbase = Hs + (wg << 3);  // warp-uniform -> broadcast
        #pragma unroll
        for (int kk = 0; kk < 64; kk++) {
            ull wp = pack2(wrow[kk]);
            const ulonglong2* hp = (const ulonglong2*)(hbase + (kk << 6));
            ulonglong2 h01 = hp[0], h23 = hp[1];
            ffma2(acc[0], h01.x, wp);
            ffma2(acc[1], h01.y, wp);
            ffma2(acc[2], h23.x, wp);
            ffma2(acc[3], h23.y, wp);
        }
        __syncthreads();
    }
}

// Build x_in transposed: g_xT[t][p][b] = t==0 ? start[p] : target[b][t-1][p]
__global__ void trans_kernel(const float* __restrict__ target,
                             const float* __restrict__ start) {
    int gid = blockIdx.x * 256 + threadIdx.x;       // 0 .. 2097151
    int t = gid >> 13, p = (gid >> 6) & 127, b = gid & 63;
    g_xT[gid] = (t == 0) ? start[p]
                         : target[(size_t)b * (TT * PP) + (t - 1) * PP + p];
}

// h0 = z @ fc_init_w^T + fc_init_b  -> slot 0 of both hidden seqs; zero c.
__global__ void init_kernel(const float* __restrict__ z,
                            const float* __restrict__ fw,
                            const float* __restrict__ fb) {
    int idx = blockIdx.x * 256 + threadIdx.x;       // 0 .. 65535 = k*64+b
    int k = idx >> 6, b = idx & 63;
    float a = fb[k];
    const float* zr = z + b * 256;
    const float* wr = fw + (size_t)k * 256;
    #pragma unroll 4
    for (int l = 0; l < 256; l++) a += zr[l] * wr[l];
    g_h1[idx] = a;
    g_h2[idx] = a;
    g_c0[idx] = 0.0f;
    g_c1[idx] = 0.0f;
}

// Pipelined stage s: blocks 0-127 = layer0 step s, blocks 128-255 = layer1 step s-1.
__global__ __launch_bounds__(256) void step_kernel(int s,
    const float* __restrict__ Wih0, const float* __restrict__ Whh0,
    const float* __restrict__ bi0,  const float* __restrict__ bh0,
    const float* __restrict__ Wih1, const float* __restrict__ Whh1,
    const float* __restrict__ bi1,  const float* __restrict__ bh1) {
    __shared__ __align__(16) float sW[32 * 65];
    __shared__ __align__(16) float sH[64 * 64];
    int layer = blockIdx.x >> 7, tile = blockIdx.x & 127;
    if (layer == 0 && s == TT) return;
    if (layer == 1 && s == 0) return;

    ull acc[4] = {0, 0, 0, 0};
    const float *bia, *bib;
    float *cst, *hout;
    if (layer == 0) {
        gemm_tile(acc, Wih0, PP, tile * 8, HH, g_xT + (size_t)s * (PP * BB), PP, sW, sH);
        gemm_tile(acc, Whh0, HH, tile * 8, HH, g_h1 + (size_t)s * SLOT, HH, sW, sH);
        hout = g_h1 + (size_t)(s + 1) * SLOT;
        cst = g_c0; bia = bi0; bib = bh0;
    } else {
        int t = s - 1;
        gemm_tile(acc, Wih1, HH, tile * 8, HH, g_h1 + (size_t)(t + 1) * SLOT, HH, sW, sH);
        gemm_tile(acc, Whh1, HH, tile * 8, HH, g_h2 + (size_t)t * SLOT, HH, sW, sH);
        hout = g_h2 + (size_t)(t + 1) * SLOT;
        cst = g_c1; bia = bi1; bib = bh1;
    }

    // Dump acc tile to smem (pitch 65: bank-conflict-free), remap to (hcol, b).
    int lane = threadIdx.x & 31, wg = threadIdx.x >> 5;
    #pragma unroll
    for (int j = 0; j < 4; j++) {
        float2 v = unpack2(acc[j]);
        sW[lane * 65 + wg * 8 + 2 * j]     = v.x;
        sW[lane * 65 + wg * 8 + 2 * j + 1] = v.y;
    }
    __syncthreads();
    #pragma unroll
    for (int q = 0; q < 2; q++) {
        int c = threadIdx.x * 2 + q;     // 0..511 = hl*64 + b
        int hl = c >> 6, b = c & 63;
        int col = tile * 8 + hl;
        float gi = sW[hl * 65 + b]        + bia[col]          + bib[col];
        float gf = sW[(8 + hl) * 65 + b]  + bia[HH + col]     + bib[HH + col];
        float gg = sW[(16 + hl) * 65 + b] + bia[2 * HH + col] + bib[2 * HH + col];
        float go = sW[(24 + hl) * 65 + b] + bia[3 * HH + col] + bib[3 * HH + col];
        float cc = sigf(gf) * cst[col * 64 + b] + sigf(gi) * tanhf(gg);
        cst[col * 64 + b] = cc;
        hout[col * 64 + b] = sigf(go) * tanhf(cc);
    }
}

// out[b][t][p] = sigmoid(h2(t) . out_w[p] + out_b[p]); grid = T*4 blocks.
__global__ __launch_bounds__(256) void out_kernel(const float* __restrict__ Wout,
                                                  const float* __restrict__ bout,
                                                  float* __restrict__ out) {
    __shared__ __align__(16) float sW[32 * 65];
    __shared__ __align__(16) float sH[64 * 64];
    int t = blockIdx.x >> 2, pt = blockIdx.x & 3;
    ull acc[4] = {0, 0, 0, 0};
    // gStride=8 makes grow(r) = pt*32 + r (plain consecutive rows).
    gemm_tile(acc, Wout, HH, pt * 32, 8, g_h2 + (size_t)(t + 1) * SLOT, HH, sW, sH);
    int lane = threadIdx.x & 31, wg = threadIdx.x >> 5;
    int p = pt * 32 + lane;
    float bo = bout[p];
    #pragma unroll
    for (int j = 0; j < 4; j++) {
        float2 v = unpack2(acc[j]);
        int b0 = wg * 8 + 2 * j;
        out[(size_t)b0 * (TT * PP) + t * PP + p]       = sigf(v.x + bo);
        out[(size_t)(b0 + 1) * (TT * PP) + t * PP + p] = sigf(v.y + bo);
    }
}

extern "C" void kernel_launch(void* const* d_in, const int* in_sizes, int n_in,
                              void* d_out, int out_size) {
    const float* z      = (const float*)d_in[0];
    const float* target = (const float*)d_in[1];
    const float* fw     = (const float*)d_in[2];
    const float* fb     = (const float*)d_in[3];
    const float* start  = (const float*)d_in[4];
    const float* Wih0   = (const float*)d_in[5];
    const float* Whh0   = (const float*)d_in[6];
    const float* bi0    = (const float*)d_in[7];
    const float* bh0    = (const float*)d_in[8];
    const float* Wih1   = (const float*)d_in[9];
    const float* Whh1   = (const float*)d_in[10];
    const float* bi1    = (const float*)d_in[11];
    const float* bh1    = (const float*)d_in[12];
    const float* outw   = (const float*)d_in[13];
    const float* outb   = (const float*)d_in[14];
    float* out = (float*)d_out;

    trans_kernel<<<(TT * PP * BB) / 256, 256>>>(target, start);
    init_kernel<<<SLOT / 256, 256>>>(z, fw, fb);
    for (int s = 0; s <= TT; s++)
        step_kernel<<<256, 256>>>(s, Wih0, Whh0, bi0, bh0, Wih1, Whh1, bi1, bh1);
    out_kernel<<<TT * 4, 256>>>(outw, outb, out);
}

// round 10
// speedup vs baseline: 2.8396x; 2.4807x over previous
#include <cuda_runtime.h>
#include <cuda_fp16.h>
#include <math.h>

#define TT 256
#define BB 64
#define HH 1024
#define PP 128
#define SLOT (HH*BB)   // 65536 floats per time-slot, k-major [k][b]

typedef unsigned long long ull;

// Static scratch (no runtime allocation).
__device__ float g_xT[TT*PP*BB];        // x_in transposed [t][p][b], 8 MB
__device__ float g_h1[(TT+1)*SLOT];     // layer0 hidden seq, slot t+1 = h1(t)
__device__ float g_h2[(TT+1)*SLOT];     // layer1 hidden seq
__device__ float g_c0[SLOT];
__device__ float g_c1[SLOT];

__device__ __forceinline__ float sigf(float x) { return 1.0f / (1.0f + __expf(-x)); }

// ---------------- fp32 packed-FFMA path (kept for init/out kernels) ----------
__device__ __forceinline__ void ffma2(ull& d, ull a, ull b) {
    asm("fma.rn.f32x2 %0, %1, %2, %0;" : "+l"(d) : "l"(a), "l"(b));
}
__device__ __forceinline__ ull pack2(float x) {
    unsigned u = __float_as_uint(x);
    return ((ull)u << 32) | (ull)u;
}
__device__ __forceinline__ float2 unpack2(ull v) {
    float2 f;
    f.x = __uint_as_float((unsigned)(v & 0xffffffffull));
    f.y = __uint_as_float((unsigned)(v >> 32));
    return f;
}

__device__ __forceinline__ void gemm_tile(ull acc[4], const float* __restrict__ W,
                                          int ldw, int rowBase, int gStride,
                                          const float* __restrict__ HT, int K,
                                          float* Ws, float* Hs) {
    const int tid = threadIdx.x, lane = tid & 31, wg = tid >> 5;
    for (int k0 = 0; k0 < K; k0 += 64) {
        #pragma unroll
        for (int q = 0; q < 2; q++) {
            int f = tid * 2 + q;
            int r = f >> 4, kc = (f & 15) << 2;
            int grow = (r >> 3) * gStride + rowBase + (r & 7);
            float4 wv = *(const float4*)(W + (size_t)grow * ldw + k0 + kc);
            float* dst = Ws + r * 65 + kc;
            dst[0] = wv.x; dst[1] = wv.y; dst[2] = wv.z; dst[3] = wv.w;
        }
        #pragma unroll
        for (int q = 0; q < 4; q++) {
            int f = tid + (q << 8);
            int kk = f >> 4, b4 = (f & 15) << 2;
            *(float4*)(Hs + kk * 64 + b4) =
                *(const float4*)(HT + (size_t)(k0 + kk) * 64 + b4);
        }
        __syncthreads();
        const float* wrow = Ws + lane * 65;
        const float* hbase = Hs + (wg << 3);
        #pragma unroll
        for (int kk = 0; kk < 64; kk++) {
            ull wp = pack2(wrow[kk]);
            const ulonglong2* hp = (const ulonglong2*)(hbase + (kk << 6));
            ulonglong2 h01 = hp[0], h23 = hp[1];
            ffma2(acc[0], h01.x, wp);
            ffma2(acc[1], h01.y, wp);
            ffma2(acc[2], h23.x, wp);
            ffma2(acc[3], h23.y, wp);
        }
        __syncthreads();
    }
}

// ---------------- tensor-core step path ----------------
__device__ __forceinline__ unsigned swz(unsigned off) {
    return off ^ ((off >> 3) & 0x70);   // SW128: flip byte bits[4:6] by row&7
}
__device__ __forceinline__ void ldmA(unsigned& r0, unsigned& r1, unsigned& r2,
                                     unsigned& r3, unsigned addr) {
    asm volatile("ldmatrix.sync.aligned.m8n8.x4.shared.b16 {%0,%1,%2,%3}, [%4];"
                 : "=r"(r0), "=r"(r1), "=r"(r2), "=r"(r3) : "r"(addr));
}
__device__ __forceinline__ void ldmBT(unsigned& r0, unsigned& r1, unsigned& r2,
                                      unsigned& r3, unsigned addr) {
    asm volatile("ldmatrix.sync.aligned.m8n8.x4.trans.shared.b16 {%0,%1,%2,%3}, [%4];"
                 : "=r"(r0), "=r"(r1), "=r"(r2), "=r"(r3) : "r"(addr));
}
__device__ __forceinline__ void mma16816(float* c, unsigned a0, unsigned a1,
                                         unsigned a2, unsigned a3,
                                         unsigned b0, unsigned b1) {
    asm volatile("mma.sync.aligned.m16n8k16.row.col.f32.f16.f16.f32 "
                 "{%0,%1,%2,%3}, {%4,%5,%6,%7}, {%8,%9}, {%0,%1,%2,%3};"
                 : "+f"(c[0]), "+f"(c[1]), "+f"(c[2]), "+f"(c[3])
                 : "r"(a0), "r"(a1), "r"(a2), "r"(a3), "r"(b0), "r"(b1));
}

// smem layout (bytes): A bufs [0,4K),[4K,8K)  B bufs [8K,16K),[16K,24K)
#define SM_A0 0
#define SM_B0 8192
#define SM_AB 4096
#define SM_BB 8192

// acc[8] += W[grow(r)][k] * HT[k][b] over tile (32 rows x 64 batch), fp16 mma.
// grow(r) = (r>>3)*HH + rowBase + (r&7). Per warp: m16 x n16 tile.
__device__ __forceinline__ void mma_gemm(float acc[8], const float* __restrict__ W,
                                         int ldw, int rowBase,
                                         const float* __restrict__ HT, int K,
                                         char* smem, unsigned smemAddr) {
    const int tid = threadIdx.x, lane = tid & 31, wid = tid >> 5;
    const int m0 = (wid & 1) * 16, n0 = (wid >> 1) * 16;
    const int nch = K >> 6;

    // staging coordinates (2 W float4s + 4 H float4s per thread per chunk)
    int rA[2], kcA[2], growA[2];
    #pragma unroll
    for (int q = 0; q < 2; q++) {
        int f = tid * 2 + q;
        rA[q] = f >> 4; kcA[q] = (f & 15) << 2;
        growA[q] = (rA[q] >> 3) * HH + rowBase + (rA[q] & 7);
    }
    int kkB[4], b4B[4];
    #pragma unroll
    for (int q = 0; q < 4; q++) {
        int f = tid + (q << 8);
        kkB[q] = f >> 4; b4B[q] = (f & 15) << 2;
    }

    float4 wR[2], hR[4];
    // prefetch chunk 0
    #pragma unroll
    for (int q = 0; q < 2; q++)
        wR[q] = *(const float4*)(W + (size_t)growA[q] * ldw + kcA[q]);
    #pragma unroll
    for (int q = 0; q < 4; q++)
        hR[q] = *(const float4*)(HT + (size_t)kkB[q] * 64 + b4B[q]);

    for (int c = 0; c < nch; c++) {
        unsigned aOff = SM_A0 + (c & 1) * SM_AB;
        unsigned bOff = SM_B0 + (c & 1) * SM_BB;
        __syncthreads();   // buffer (c&1) free (compute from chunk c-2 done)
        // store W chunk: [r][k] halfs, 128B rows, swizzled
        #pragma unroll
        for (int q = 0; q < 2; q++) {
            half2 lo = __floats2half2_rn(wR[q].x, wR[q].y);
            half2 hi = __floats2half2_rn(wR[q].z, wR[q].w);
            unsigned off = aOff + swz((unsigned)(rA[q] * 128 + kcA[q] * 2));
            half2* d = (half2*)(smem + off);
            d[0] = lo; d[1] = hi;
        }
        // store H chunk: [k][b] halfs, 128B rows, swizzled
        #pragma unroll
        for (int q = 0; q < 4; q++) {
            half2 lo = __floats2half2_rn(hR[q].x, hR[q].y);
            half2 hi = __floats2half2_rn(hR[q].z, hR[q].w);
            unsigned off = bOff + swz((unsigned)(kkB[q] * 128 + b4B[q] * 2));
            half2* d = (half2*)(smem + off);
            d[0] = lo; d[1] = hi;
        }
        // prefetch next chunk while mma runs
        if (c + 1 < nch) {
            int k0 = (c + 1) << 6;
            #pragma unroll
            for (int q = 0; q < 2; q++)
                wR[q] = *(const float4*)(W + (size_t)growA[q] * ldw + k0 + kcA[q]);
            #pragma unroll
            for (int q = 0; q < 4; q++)
                hR[q] = *(const float4*)(HT + (size_t)(k0 + kkB[q]) * 64 + b4B[q]);
        }
        __syncthreads();
        // 4 k16 steps
        int j = lane >> 3, l = lane & 7;
        #pragma unroll
        for (int ks = 0; ks < 4; ks++) {
            unsigned a0, a1, a2, a3, b0, b1, b2, b3;
            unsigned aAddr = smemAddr + aOff +
                swz((unsigned)((m0 + (lane & 15)) * 128 + ks * 32 + ((lane >> 4) << 4)));
            ldmA(a0, a1, a2, a3, aAddr);
            unsigned bAddr = smemAddr + bOff +
                swz((unsigned)((ks * 16 + (j & 1) * 8 + l) * 128 + n0 * 2 + ((j >> 1) << 4)));
            ldmBT(b0, b1, b2, b3, bAddr);
            mma16816(acc + 0, a0, a1, a2, a3, b0, b1);
            mma16816(acc + 4, a0, a1, a2, a3, b2, b3);
        }
    }
}

// Build x_in transposed: g_xT[t][p][b] = t==0 ? start[p] : target[b][t-1][p]
__global__ void trans_kernel(const float* __restrict__ target,
                             const float* __restrict__ start) {
    int gid = blockIdx.x * 256 + threadIdx.x;
    int t = gid >> 13, p = (gid >> 6) & 127, b = gid & 63;
    g_xT[gid] = (t == 0) ? start[p]
                         : target[(size_t)b * (TT * PP) + (t - 1) * PP + p];
}

// h0 = z @ fc_init_w^T + fc_init_b  -> slot 0 of both hidden seqs; zero c.
__global__ void init_kernel(const float* __restrict__ z,
                            const float* __restrict__ fw,
                            const float* __restrict__ fb) {
    int idx = blockIdx.x * 256 + threadIdx.x;
    int k = idx >> 6, b = idx & 63;
    float a = fb[k];
    const float* zr = z + b * 256;
    const float* wr = fw + (size_t)k * 256;
    #pragma unroll 4
    for (int l = 0; l < 256; l++) a += zr[l] * wr[l];
    g_h1[idx] = a;
    g_h2[idx] = a;
    g_c0[idx] = 0.0f;
    g_c1[idx] = 0.0f;
}

// Pipelined stage s: blocks 0-127 = layer0 step s, blocks 128-255 = layer1 step s-1.
__global__ __launch_bounds__(256, 2) void step_kernel(int s,
    const float* __restrict__ Wih0, const float* __restrict__ Whh0,
    const float* __restrict__ bi0,  const float* __restrict__ bh0,
    const float* __restrict__ Wih1, const float* __restrict__ Whh1,
    const float* __restrict__ bi1,  const float* __restrict__ bh1) {
    __shared__ __align__(128) char smem[24576];
    int layer = blockIdx.x >> 7, tile = blockIdx.x & 127;
    if (layer == 0 && s == TT) return;
    if (layer == 1 && s == 0) return;
    unsigned smemAddr = (unsigned)__cvta_generic_to_shared(smem);

    float acc[8] = {0, 0, 0, 0, 0, 0, 0, 0};
    const float *bia, *bib;
    float *cst, *hout;
    if (layer == 0) {
        mma_gemm(acc, Wih0, PP, tile * 8, g_xT + (size_t)s * (PP * BB), PP, smem, smemAddr);
        mma_gemm(acc, Whh0, HH, tile * 8, g_h1 + (size_t)s * SLOT, HH, smem, smemAddr);
        hout = g_h1 + (size_t)(s + 1) * SLOT;
        cst = g_c0; bia = bi0; bib = bh0;
    } else {
        int t = s - 1;
        mma_gemm(acc, Wih1, HH, tile * 8, g_h1 + (size_t)(t + 1) * SLOT, HH, smem, smemAddr);
        mma_gemm(acc, Whh1, HH, tile * 8, g_h2 + (size_t)t * SLOT, HH, smem, smemAddr);
        hout = g_h2 + (size_t)(t + 1) * SLOT;
        cst = g_c1; bia = bi1; bib = bh1;
    }

    // acc -> smem (fp32, pitch 65), remap to (hcol, b) for elementwise.
    int lane = threadIdx.x & 31, wid = threadIdx.x >> 5;
    int m0 = (wid & 1) * 16, n0 = (wid >> 1) * 16;
    int gid = lane >> 2, tig = lane & 3;
    float* sOut = (float*)smem;
    __syncthreads();
    #pragma unroll
    for (int t2 = 0; t2 < 2; t2++) {
        int bcol = n0 + t2 * 8 + 2 * tig;
        int row = m0 + gid;
        sOut[row * 65 + bcol]           = acc[4 * t2 + 0];
        sOut[row * 65 + bcol + 1]       = acc[4 * t2 + 1];
        sOut[(row + 8) * 65 + bcol]     = acc[4 * t2 + 2];
        sOut[(row + 8) * 65 + bcol + 1] = acc[4 * t2 + 3];
    }
    __syncthreads();
    #pragma unroll
    for (int q = 0; q < 2; q++) {
        int c = threadIdx.x * 2 + q;     // 0..511 = hl*64 + b
        int hl = c >> 6, b = c & 63;
        int col = tile * 8 + hl;
        float gi = sOut[hl * 65 + b]        + bia[col]          + bib[col];
        float gf = sOut[(8 + hl) * 65 + b]  + bia[HH + col]     + bib[HH + col];
        float gg = sOut[(16 + hl) * 65 + b] + bia[2 * HH + col] + bib[2 * HH + col];
        float go = sOut[(24 + hl) * 65 + b] + bia[3 * HH + col] + bib[3 * HH + col];
        float cc = sigf(gf) * cst[col * 64 + b] + sigf(gi) * tanhf(gg);
        cst[col * 64 + b] = cc;
        hout[col * 64 + b] = sigf(go) * tanhf(cc);
    }
}

// out[b][t][p] = sigmoid(h2(t) . out_w[p] + out_b[p]); grid = T*4 blocks (fp32).
__global__ __launch_bounds__(256) void out_kernel(const float* __restrict__ Wout,
                                                  const float* __restrict__ bout,
                                                  float* __restrict__ out) {
    __shared__ __align__(16) float sW[32 * 65];
    __shared__ __align__(16) float sH[64 * 64];
    int t = blockIdx.x >> 2, pt = blockIdx.x & 3;
    ull acc[4] = {0, 0, 0, 0};
    gemm_tile(acc, Wout, HH, pt * 32, 8, g_h2 + (size_t)(t + 1) * SLOT, HH, sW, sH);
    int lane = threadIdx.x & 31, wg = threadIdx.x >> 5;
    int p = pt * 32 + lane;
    float bo = bout[p];
    #pragma unroll
    for (int j = 0; j < 4; j++) {
        float2 v = unpack2(acc[j]);
        int b0 = wg * 8 + 2 * j;
        out[(size_t)b0 * (TT * PP) + t * PP + p]       = sigf(v.x + bo);
        out[(size_t)(b0 + 1) * (TT * PP) + t * PP + p] = sigf(v.y + bo);
    }
}

extern "C" void kernel_launch(void* const* d_in, const int* in_sizes, int n_in,
                              void* d_out, int out_size) {
    const float* z      = (const float*)d_in[0];
    const float* target = (const float*)d_in[1];
    const float* fw     = (const float*)d_in[2];
    const float* fb     = (const float*)d_in[3];
    const float* start  = (const float*)d_in[4];
    const float* Wih0   = (const float*)d_in[5];
    const float* Whh0   = (const float*)d_in[6];
    const float* bi0    = (const float*)d_in[7];
    const float* bh0    = (const float*)d_in[8];
    const float* Wih1   = (const float*)d_in[9];
    const float* Whh1   = (const float*)d_in[10];
    const float* bi1    = (const float*)d_in[11];
    const float* bh1    = (const float*)d_in[12];
    const float* outw   = (const float*)d_in[13];
    const float* outb   = (const float*)d_in[14];
    float* out = (float*)d_out;

    trans_kernel<<<(TT * PP * BB) / 256, 256>>>(target, start);
    init_kernel<<<SLOT / 256, 256>>>(z, fw, fb);
    for (int s = 0; s <= TT; s++)
        step_kernel<<<256, 256>>>(s, Wih0, Whh0, bi0, bh0, Wih1, Whh1, bi1, bh1);
    out_kernel<<<TT * 4, 256>>>(outw, outb, out);
}

// round 11
// speedup vs baseline: 8.1827x; 2.8817x over previous
#include <cuda_runtime.h>
#include <cuda_fp16.h>
#include <math.h>

#define TT 256
#define BB 64
#define HH 1024
#define PP 128
#define SLOT (HH*BB)   // 65536 elems per time-slot, k-major [k][b]

// ---------------- static scratch (no runtime allocation) ----------------
__device__ __align__(128) __half g_xT[TT*PP*BB];      // x_in [t][p][b] fp16
__device__ __align__(128) __half g_h1[(TT+1)*SLOT];   // layer0 hidden, fp16
__device__ __align__(128) __half g_h2[(TT+1)*SLOT];   // layer1 hidden, fp16
__device__ float g_c0[SLOT];
__device__ float g_c1[SLOT];
// fp16 weight images, tile-contiguous: [tile][64 rows][K]
// gate-interleaved rows: grow(r) = (r>>4)*1024 + tile*16 + (r&15)
__device__ __align__(128) __half g_wA0[64*64*128];    // W_ih_l0
__device__ __align__(128) __half g_wB0[64*64*1024];   // W_hh_l0
__device__ __align__(128) __half g_wA1[64*64*1024];   // W_ih_l1
__device__ __align__(128) __half g_wB1[64*64*1024];   // W_hh_l1
__device__ __align__(128) __half g_wOut[2*64*1024];   // out_w (plain rows)

__device__ __forceinline__ float sigf(float x) { return 1.0f / (1.0f + __expf(-x)); }
__device__ __forceinline__ unsigned swz(unsigned o) { return o ^ ((o >> 3) & 0x70); }

__device__ __forceinline__ void cpa16(unsigned dst, const void* src) {
    asm volatile("cp.async.cg.shared.global [%0], [%1], 16;\n" :: "r"(dst), "l"(src));
}
__device__ __forceinline__ void cpa_commit() { asm volatile("cp.async.commit_group;\n"); }
__device__ __forceinline__ void cpa_wait1()  { asm volatile("cp.async.wait_group 1;\n"); }
__device__ __forceinline__ void cpa_wait0()  { asm volatile("cp.async.wait_group 0;\n"); }

__device__ __forceinline__ void ldmA(unsigned& r0, unsigned& r1, unsigned& r2,
                                     unsigned& r3, unsigned addr) {
    asm volatile("ldmatrix.sync.aligned.m8n8.x4.shared.b16 {%0,%1,%2,%3}, [%4];"
                 : "=r"(r0), "=r"(r1), "=r"(r2), "=r"(r3) : "r"(addr));
}
__device__ __forceinline__ void ldmBT(unsigned& r0, unsigned& r1, unsigned& r2,
                                      unsigned& r3, unsigned addr) {
    asm volatile("ldmatrix.sync.aligned.m8n8.x4.trans.shared.b16 {%0,%1,%2,%3}, [%4];"
                 : "=r"(r0), "=r"(r1), "=r"(r2), "=r"(r3) : "r"(addr));
}
__device__ __forceinline__ void mma16816(float* c, unsigned a0, unsigned a1,
                                         unsigned a2, unsigned a3,
                                         unsigned b0, unsigned b1) {
    asm volatile("mma.sync.aligned.m16n8k16.row.col.f32.f16.f16.f32 "
                 "{%0,%1,%2,%3}, {%4,%5,%6,%7}, {%8,%9}, {%0,%1,%2,%3};"
                 : "+f"(c[0]), "+f"(c[1]), "+f"(c[2]), "+f"(c[3])
                 : "r"(a0), "r"(a1), "r"(a2), "r"(a3), "r"(b0), "r"(b1));
}

// Block tile: 64 rows x 64 batch. 8 warps: warp tile m16 x n32,
// m0=(wid&3)*16 (gate), n0=(wid>>2)*32. K in 64-chunks, 3-stage cp.async pipe.
// Wimg: [64 rows][K] fp16 row-major. B: [K][64] fp16 (contiguous 128B k-rows).
// smem stages at (c%3)*16384: A at +0 (8KB, 128B rows, SW128), B at +8192.
__device__ __forceinline__ void mma_gemm(float acc[16], const __half* __restrict__ Wimg,
                                         const __half* __restrict__ B, int K,
                                         unsigned smemAddr) {
    const int tid = threadIdx.x, lane = tid & 31, wid = tid >> 5;
    const int m0 = (wid & 3) * 16, n0 = (wid >> 2) * 32;
    const int nch = K >> 6;
    __syncthreads();   // protect smem reuse across consecutive calls

    auto stage = [&](int c) {
        unsigned base = smemAddr + (unsigned)(c % 3) * 16384u;
        int k0 = c << 6;
        #pragma unroll
        for (int q = 0; q < 2; q++) {          // A: 512 x 16B units
            int f = tid * 2 + q, r = f >> 3, seg = f & 7;
            cpa16(base + swz((unsigned)(r * 128 + seg * 16)),
                  Wimg + (size_t)r * K + k0 + seg * 8);
        }
        const __half* bsrc = B + ((size_t)k0 << 6);
        #pragma unroll
        for (int q = 0; q < 2; q++) {          // B: contiguous 8KB chunk
            int f = tid * 2 + q;
            cpa16(base + 8192u + swz((unsigned)(f * 16)), bsrc + f * 8);
        }
        cpa_commit();
    };

    stage(0);
    if (nch > 1) stage(1);
    for (int c = 0; c < nch; c++) {
        if (c + 1 < nch) cpa_wait1(); else cpa_wait0();
        __syncthreads();                 // chunk c visible; buf (c+2)%3 free
        if (c + 2 < nch) stage(c + 2);
        unsigned base = smemAddr + (unsigned)(c % 3) * 16384u;
        int j = lane >> 3, l = lane & 7;
        #pragma unroll
        for (int ks = 0; ks < 4; ks++) {
            unsigned a0, a1, a2, a3, b0, b1, b2, b3, b4, b5, b6, b7;
            ldmA(a0, a1, a2, a3, base +
                 swz((unsigned)((m0 + (lane & 15)) * 128 + ks * 32 + ((lane >> 4) << 4))));
            unsigned brow = (unsigned)((ks * 16 + (j & 1) * 8 + l) * 128 + ((j >> 1) << 4));
            ldmBT(b0, b1, b2, b3, base + 8192u + swz(brow + n0 * 2));
            ldmBT(b4, b5, b6, b7, base + 8192u + swz(brow + (n0 + 16) * 2));
            mma16816(acc + 0,  a0, a1, a2, a3, b0, b1);
            mma16816(acc + 4,  a0, a1, a2, a3, b2, b3);
            mma16816(acc + 8,  a0, a1, a2, a3, b4, b5);
            mma16816(acc + 12, a0, a1, a2, a3, b6, b7);
        }
    }
}

// Dump warp acc fragments into fp32 smem [64 rows][pitch 65].
__device__ __forceinline__ void acc_to_smem(const float acc[16], float* sOut) {
    int lane = threadIdx.x & 31, wid = threadIdx.x >> 5;
    int m0 = (wid & 3) * 16, n0 = (wid >> 2) * 32;
    int gid = lane >> 2, tig = lane & 3;
    #pragma unroll
    for (int jj = 0; jj < 4; jj++) {
        int col = n0 + jj * 8 + 2 * tig, row = m0 + gid;
        sOut[row * 65 + col]           = acc[4 * jj + 0];
        sOut[row * 65 + col + 1]       = acc[4 * jj + 1];
        sOut[(row + 8) * 65 + col]     = acc[4 * jj + 2];
        sOut[(row + 8) * 65 + col + 1] = acc[4 * jj + 3];
    }
}

// ---------------- one-time prep ----------------
// Weight image gather: dst[tile][r][k] = src[grow(r)][k], grow=(r>>4)*1024+tile*16+(r&15)
__global__ void wprep_gate(__half* dst, const float* __restrict__ src, int K) {
    int idx = blockIdx.x * 256 + threadIdx.x;        // 64*64*K total
    int k = idx & (K - 1);
    int rr = idx / K;
    int r = rr & 63, tile = rr >> 6;
    int grow = ((r >> 4) << 10) + tile * 16 + (r & 15);
    dst[idx] = __float2half(src[(size_t)grow * K + k]);
}
__global__ void wprep_out(const float* __restrict__ src) {
    int idx = blockIdx.x * 256 + threadIdx.x;        // 131072
    g_wOut[idx] = __float2half(src[idx]);
}
// x_in transposed fp16: g_xT[t][p][b] = t==0 ? start[p] : target[b][t-1][p]
__global__ void trans_kernel(const float* __restrict__ target,
                             const float* __restrict__ start) {
    int gid = blockIdx.x * 256 + threadIdx.x;
    int t = gid >> 13, p = (gid >> 6) & 127, b = gid & 63;
    float v = (t == 0) ? start[p]
                       : target[(size_t)b * (TT * PP) + (t - 1) * PP + p];
    g_xT[gid] = __float2half(v);
}
// h0 = z @ fc_init_w^T + fc_init_b -> slot 0 (fp16); c = 0.
__global__ void init_kernel(const float* __restrict__ z,
                            const float* __restrict__ fw,
                            const float* __restrict__ fb) {
    int idx = blockIdx.x * 256 + threadIdx.x;        // k*64+b
    int k = idx >> 6, b = idx & 63;
    float a = fb[k];
    const float* zr = z + b * 256;
    const float* wr = fw + (size_t)k * 256;
    #pragma unroll 4
    for (int l = 0; l < 256; l++) a += zr[l] * wr[l];
    __half h = __float2half(a);
    g_h1[idx] = h;
    g_h2[idx] = h;
    g_c0[idx] = 0.0f;
    g_c1[idx] = 0.0f;
}

// ---------------- pipelined LSTM stage ----------------
// Stage s: blocks 0-63 = layer0 step s, blocks 64-127 = layer1 step s-1.
__global__ __launch_bounds__(256) void step_kernel(int s,
    const float* __restrict__ bi0, const float* __restrict__ bh0,
    const float* __restrict__ bi1, const float* __restrict__ bh1) {
    __shared__ __align__(128) char smem[49152];
    unsigned smemAddr = (unsigned)__cvta_generic_to_shared(smem);
    int layer = blockIdx.x >> 6, tile = blockIdx.x & 63;
    if (layer == 0 && s == TT) return;
    if (layer == 1 && s == 0) return;

    float acc[16] = {};
    const float *bia, *bib;
    float* cst;
    __half* hout;
    if (layer == 0) {
        mma_gemm(acc, g_wA0 + (size_t)tile * 64 * 128, g_xT + (size_t)s * (PP * BB),
                 128, smemAddr);
        mma_gemm(acc, g_wB0 + (size_t)tile * 64 * 1024, g_h1 + (size_t)s * SLOT,
                 1024, smemAddr);
        hout = g_h1 + (size_t)(s + 1) * SLOT;
        cst = g_c0; bia = bi0; bib = bh0;
    } else {
        int t = s - 1;
        mma_gemm(acc, g_wA1 + (size_t)tile * 64 * 1024, g_h1 + (size_t)(t + 1) * SLOT,
                 1024, smemAddr);
        mma_gemm(acc, g_wB1 + (size_t)tile * 64 * 1024, g_h2 + (size_t)t * SLOT,
                 1024, smemAddr);
        hout = g_h2 + (size_t)(t + 1) * SLOT;
        cst = g_c1; bia = bi1; bib = bh1;
    }

    float* sOut = (float*)smem;
    __syncthreads();
    acc_to_smem(acc, sOut);
    __syncthreads();
    // rows 0-15: gate i (h-cols tile*16+hl), 16-31: f, 32-47: g, 48-63: o
    #pragma unroll
    for (int q = 0; q < 4; q++) {
        int idx = q * 256 + threadIdx.x;     // 0..1023 = hl*64 + b
        int b = idx & 63, hl = idx >> 6;
        int col = tile * 16 + hl;
        float gi = sOut[hl * 65 + b]        + bia[col]        + bib[col];
        float gf = sOut[(16 + hl) * 65 + b] + bia[1024 + col] + bib[1024 + col];
        float gg = sOut[(32 + hl) * 65 + b] + bia[2048 + col] + bib[2048 + col];
        float go = sOut[(48 + hl) * 65 + b] + bia[3072 + col] + bib[3072 + col];
        float cc = sigf(gf) * cst[col * 64 + b] + sigf(gi) * tanhf(gg);
        cst[col * 64 + b] = cc;
        hout[col * 64 + b] = __float2half(sigf(go) * tanhf(cc));
    }
}

// out[b][t][p] = sigmoid(h2(t) . out_w[p] + out_b[p]); grid = TT*2.
__global__ __launch_bounds__(256) void out_kernel(const float* __restrict__ bout,
                                                  float* __restrict__ out) {
    __shared__ __align__(128) char smem[49152];
    unsigned smemAddr = (unsigned)__cvta_generic_to_shared(smem);
    int t = blockIdx.x >> 1, tile = blockIdx.x & 1;
    float acc[16] = {};
    mma_gemm(acc, g_wOut + (size_t)tile * 64 * 1024, g_h2 + (size_t)(t + 1) * SLOT,
             1024, smemAddr);
    float* sOut = (float*)smem;
    __syncthreads();
    acc_to_smem(acc, sOut);
    __syncthreads();
    #pragma unroll
    for (int q = 0; q < 16; q++) {
        int idx = q * 256 + threadIdx.x;     // 0..4095 = b*64 + p
        int p = idx & 63, b = idx >> 6;
        float v = sigf(sOut[p * 65 + b] + bout[tile * 64 + p]);
        out[(size_t)b * (TT * PP) + t * PP + tile * 64 + p] = v;
    }
}

extern "C" void kernel_launch(void* const* d_in, const int* in_sizes, int n_in,
                              void* d_out, int out_size) {
    const float* z      = (const float*)d_in[0];
    const float* target = (const float*)d_in[1];
    const float* fw     = (const float*)d_in[2];
    const float* fb     = (const float*)d_in[3];
    const float* start  = (const float*)d_in[4];
    const float* Wih0   = (const float*)d_in[5];
    const float* Whh0   = (const float*)d_in[6];
    const float* bi0    = (const float*)d_in[7];
    const float* bh0    = (const float*)d_in[8];
    const float* Wih1   = (const float*)d_in[9];
    const float* Whh1   = (const float*)d_in[10];
    const float* bi1    = (const float*)d_in[11];
    const float* bh1    = (const float*)d_in[12];
    const float* outw   = (const float*)d_in[13];
    const float* outb   = (const float*)d_in[14];
    float* out = (float*)d_out;

    __half *wA0, *wB0, *wA1, *wB1;
    cudaGetSymbolAddress((void**)&wA0, g_wA0);
    cudaGetSymbolAddress((void**)&wB0, g_wB0);
    cudaGetSymbolAddress((void**)&wA1, g_wA1);
    cudaGetSymbolAddress((void**)&wB1, g_wB1);

    wprep_gate<<<(64 * 64 * 128) / 256, 256>>>(wA0, Wih0, 128);
    wprep_gate<<<(64 * 64 * 1024) / 256, 256>>>(wB0, Whh0, 1024);
    wprep_gate<<<(64 * 64 * 1024) / 256, 256>>>(wA1, Wih1, 1024);
    wprep_gate<<<(64 * 64 * 1024) / 256, 256>>>(wB1, Whh1, 1024);
    wprep_out<<<(2 * 64 * 1024) / 256, 256>>>(outw);
    trans_kernel<<<(TT * PP * BB) / 256, 256>>>(target, start);
    init_kernel<<<SLOT / 256, 256>>>(z, fw, fb);
    for (int s = 0; s <= TT; s++)
        step_kernel<<<128, 256>>>(s, bi0, bh0, bi1, bh1);
    out_kernel<<<TT * 2, 256>>>(outb, out);
}